// round 8
// baseline (speedup 1.0000x reference)
#include <cuda_runtime.h>
#include <cstdint>

#define B_  32
#define T_  2048
#define D_  256
#define H_  256
#define A_  18
#define G4  1024
#define M_  (B_*T_)          // 65536

#define LOGITS_OFF 0
#define LAST_OFF   ((size_t)M_*A_)                   // 1179648
#define C_OFF      (LAST_OFF + (size_t)M_*H_)        // 17956864
#define HF_OFF     (C_OFF + (size_t)B_*H_)           // 17965056

// 256 MB scratch for pre-computed input gates (x @ Wx + b)
__device__ float g_scr[(size_t)M_ * G4];

// ---------------- f32x2 packed helpers ----------------
__device__ __forceinline__ unsigned long long pk2(float lo, float hi){
    unsigned long long r;
    asm("mov.b64 %0, {%1,%2};" : "=l"(r) : "f"(lo), "f"(hi));
    return r;
}
__device__ __forceinline__ void fma2(unsigned long long &d, unsigned long long a, unsigned long long b){
    asm("fma.rn.f32x2 %0, %1, %2, %0;" : "+l"(d) : "l"(a), "l"(b));
}
__device__ __forceinline__ float2 up2(unsigned long long v){
    float2 f;
    asm("mov.b64 {%0,%1}, %2;" : "=f"(f.x), "=f"(f.y) : "l"(v));
    return f;
}

__device__ __forceinline__ float sigf(float x){
    return 1.0f / (1.0f + __expf(-x));
}
__device__ __forceinline__ float tanh_fast(float x){
    return 1.0f - 2.0f / (1.0f + __expf(2.0f * x));
}

// ---------------- mbarrier / DSMEM helpers ----------------
__device__ __forceinline__ void mbar_init(unsigned int a, unsigned int cnt){
    asm volatile("mbarrier.init.shared.b64 [%0], %1;" :: "r"(a), "r"(cnt) : "memory");
}
__device__ __forceinline__ void mbar_expect(unsigned int a, unsigned int tx){
    asm volatile("mbarrier.arrive.expect_tx.shared.b64 _, [%0], %1;" :: "r"(a), "r"(tx) : "memory");
}
// CTA-scope acquire: DSMEM-delivered smem data needs no global ordering.
__device__ __forceinline__ void mbar_wait(unsigned int a, unsigned int par){
    asm volatile(
        "{\n\t.reg .pred P;\n"
        "LAB_%=:\n\t"
        "mbarrier.try_wait.parity.acquire.cta.shared::cta.b64 P, [%0], %1, 0x989680;\n\t"
        "@P bra DONE_%=;\n\t"
        "bra LAB_%=;\n"
        "DONE_%=:\n\t}"
        :: "r"(a), "r"(par) : "memory");
}
__device__ __forceinline__ unsigned int mapa_(unsigned int a, unsigned int r){
    unsigned int d;
    asm("mapa.shared::cluster.u32 %0, %1, %2;" : "=r"(d) : "r"(a), "r"(r));
    return d;
}
__device__ __forceinline__ void st_async64(unsigned int dst, unsigned long long v, unsigned int mbar){
    asm volatile("st.async.weak.shared::cluster.mbarrier::complete_tx::bytes.b64 [%0], %1, [%2];"
                 :: "r"(dst), "l"(v), "r"(mbar) : "memory");
}
__device__ __forceinline__ void cluster_sync_(){
    asm volatile("barrier.cluster.arrive.aligned;" ::: "memory");
    asm volatile("barrier.cluster.wait.aligned;"   ::: "memory");
}

// ======================================================================
// Kernel 1: pre-GEMM  G[m][c] = x[m,:] @ W[0:256, c] + b[c]
// ======================================================================
#define PG_BM 128
#define PG_BN 128
#define PG_BK 16

__global__ __launch_bounds__(256,2) void pregemm_k(
    const float* __restrict__ x, const float* __restrict__ W,
    const float* __restrict__ bias)
{
    __shared__ float a_s[PG_BK][PG_BM];
    __shared__ float b_s[PG_BK][PG_BN];

    int tid = threadIdx.x;
    int m0 = blockIdx.y * PG_BM;
    int n0 = blockIdx.x * PG_BN;
    int tx = tid & 15;
    int ty = tid >> 4;

    unsigned long long acc[8][4];
#pragma unroll
    for (int i = 0; i < 8; i++)
#pragma unroll
        for (int j = 0; j < 4; j++) acc[i][j] = 0ull;

    for (int k0 = 0; k0 < D_; k0 += PG_BK){
#pragma unroll
        for (int i = 0; i < 2; i++){
            int f4 = tid*2 + i;
            int m  = f4 >> 2;
            int kq = f4 & 3;
            float4 v = *(const float4*)&x[(size_t)(m0+m)*D_ + k0 + kq*4];
            a_s[kq*4+0][m] = v.x; a_s[kq*4+1][m] = v.y;
            a_s[kq*4+2][m] = v.z; a_s[kq*4+3][m] = v.w;
        }
#pragma unroll
        for (int i = 0; i < 2; i++){
            int f4 = tid*2 + i;
            int row = f4 >> 5, cq = f4 & 31;
            float4 v = *(const float4*)&W[(size_t)(k0+row)*G4 + n0 + cq*4];
            *(float4*)&b_s[row][cq*4] = v;
        }
        __syncthreads();
#pragma unroll
        for (int kk = 0; kk < PG_BK; kk++){
            float4 a0 = *(float4*)&a_s[kk][ty*8];
            float4 a1 = *(float4*)&a_s[kk][ty*8+4];
            float4 b0 = *(float4*)&b_s[kk][tx*4];
            float4 b1 = *(float4*)&b_s[kk][64 + tx*4];
            unsigned long long bp0 = pk2(b0.x,b0.y), bp1 = pk2(b0.z,b0.w);
            unsigned long long bp2 = pk2(b1.x,b1.y), bp3 = pk2(b1.z,b1.w);
            float ar[8] = {a0.x,a0.y,a0.z,a0.w,a1.x,a1.y,a1.z,a1.w};
#pragma unroll
            for (int i = 0; i < 8; i++){
                unsigned long long ap = pk2(ar[i], ar[i]);
                fma2(acc[i][0], ap, bp0);
                fma2(acc[i][1], ap, bp1);
                fma2(acc[i][2], ap, bp2);
                fma2(acc[i][3], ap, bp3);
            }
        }
        __syncthreads();
    }

    float4 bv0 = *(const float4*)&bias[n0 + tx*4];
    float4 bv1 = *(const float4*)&bias[n0 + 64 + tx*4];
#pragma unroll
    for (int i = 0; i < 8; i++){
        float2 l0 = up2(acc[i][0]), h0 = up2(acc[i][1]);
        float2 l1 = up2(acc[i][2]), h1 = up2(acc[i][3]);
        size_t row = (size_t)(m0 + ty*8 + i)*G4;
        *(float4*)&g_scr[row + n0 + tx*4] =
            make_float4(l0.x+bv0.x, l0.y+bv0.y, h0.x+bv0.z, h0.y+bv0.w);
        *(float4*)&g_scr[row + n0 + 64 + tx*4] =
            make_float4(l1.x+bv1.x, l1.y+bv1.y, h1.x+bv1.z, h1.y+bv1.w);
    }
}

// ======================================================================
// Kernel 2: recurrent LSTM.
// 16 clusters x 8 CTAs, cluster = 2 batches, CTA = 32 units.
// 512 threads = 16 warps. Warp w = units {2w, 2w+1} (u_lo = lane>>4),
// 16 k-chunks of 16 k (kq = lane&15). Thread: 4 gates x 2 batches x 16 k
// = 64 fma2, weights 32 u64 in registers. 4-level in-warp butterfly puts
// the 8 (batch,gate) combos on lane pairs. h exchange: st.async from
// lanes 0-15 of each warp; mbarrier complete_tx, CTA-scope acquire wait.
// ======================================================================
#define HRANK  68                 // floats per rank slot: 64 data + 4 pad
#define SLOT_B (HRANK*4)          // 272 B
#define PHASE_B (8*SLOT_B)        // 2176 B

__global__ __launch_bounds__(512,1) __cluster_dims__(8,1,1)
void lstm_rec_k(const float* __restrict__ W, const int* __restrict__ seq_lens,
                const float* __restrict__ c_in, const float* __restrict__ h_in,
                float* __restrict__ out)
{
    // h_s[phase][src rank][batch*32 + unit_local] (+4 pad per slot)
    __shared__ __align__(16) float h_s[2][8][HRANK];
    __shared__ __align__(8) unsigned long long barr[2];

    int tid  = threadIdx.x;
    int w    = tid >> 5, lane = tid & 31;
    int rank = blockIdx.x & 7, cl = blockIdx.x >> 3;
    int u_lo = lane >> 4;                // 0..1
    int kq   = lane & 15;                // k-chunk: k in [16kq, 16kq+16)
    int c_id = kq & 7;
    int b_c  = (c_id >> 2) & 1;          // this lane's combo batch
    int g_c  = c_id & 3;                 // this lane's combo gate
    int u    = rank*32 + w*2 + u_lo;     // global unit
    int bg_c = cl*2 + b_c;
    int gcol_c = g_c*256 + u;

    // --- weights: 4 gates x 16 k (chunk kq) in 32 u64 registers ---
    const float* Wh = W + (size_t)D_*G4;
    unsigned long long wreg[4][8];
#pragma unroll
    for (int g = 0; g < 4; g++){
        int gc = g*256 + u;
#pragma unroll
        for (int j = 0; j < 8; j++){
            int k = kq*16 + 2*j;
            wreg[g][j] = pk2(Wh[(size_t)k*G4 + gc], Wh[(size_t)(k+1)*G4 + gc]);
        }
    }

    unsigned int hsm    = (unsigned int)__cvta_generic_to_shared(&h_s[0][0][0]);
    unsigned int bar_lo = (unsigned int)__cvta_generic_to_shared(&barr[0]);

    // sender role (lanes 0..15 of each warp): dest rank + batch
    int r_dst = lane & 7;
    int b_s   = (lane >> 3) & 1;
    unsigned int dst_base = mapa_(hsm, (unsigned)r_dst)
                          + (unsigned)rank*SLOT_B
                          + (unsigned)((b_s*32 + w*2)*4);
    unsigned int dst_bar  = mapa_(bar_lo, (unsigned)r_dst);
    bool is_snd = (lane < 16);
    // shfl sources for the (b_s, unit 2w / 2w+1) pair: writer lanes
    int src_lo = b_s*4;          // u_lo=0 writer for batch b_s
    int src_hi = 16 + b_s*4;     // u_lo=1 writer for batch b_s

    if (tid == 0){
        mbar_init(bar_lo,     1);
        mbar_init(bar_lo + 8, 1);
        mbar_expect(bar_lo,     2048);   // init broadcast (phase 0)
        mbar_expect(bar_lo + 8, 2048);   // step-0 sends (phase 1)
    }

    // writers: dup=0, g_c==0 -> kq in {0,4}; own state of (b_c, u)
    bool is_wr  = (kq == 0) || (kq == 4);
    bool is_wr2 = is_wr && (u_lo == 0);
    float c_r = 0.f, h_r = 0.f; int slen = 0;
    if (is_wr){
        c_r  = c_in[(size_t)bg_c*H_ + u];
        h_r  = h_in[(size_t)bg_c*H_ + u];
        slen = seq_lens[bg_c];
    }

    __syncthreads();
    cluster_sync_();   // barriers armed cluster-wide before any st.async

    // --- initial h broadcast into phase-0 buffer ---
    {
        float v_lo = __shfl_sync(0xffffffffu, h_r, src_lo);
        float v_hi = __shfl_sync(0xffffffffu, h_r, src_hi);
        if (is_snd) st_async64(dst_base, pk2(v_lo, v_hi), dst_bar);
    }

    float pre = g_scr[((size_t)bg_c*T_ + 0)*G4 + gcol_c];

    for (int t = 0; t < T_; t++){
        int p   = t & 1;
        int par = (t >> 1) & 1;
        mbar_wait(bar_lo + p*8, (unsigned)par);
        if (tid == 0) mbar_expect(bar_lo + p*8, 2048);   // re-arm for t+2

        int tn = (t+1 < T_) ? t+1 : t;
        float pre_n = g_scr[((size_t)bg_c*T_ + tn)*G4 + gcol_c];

        // --- gemm: acc[g][b] over this thread's 16-k chunk ---
        // chunk kq lives at rank slot (kq>>1), offset (kq&1)*16 + b*32
        const ulonglong2* h0 = (const ulonglong2*)
            &h_s[p][kq >> 1][(kq & 1)*16 + 0];
        const ulonglong2* h1 = (const ulonglong2*)
            &h_s[p][kq >> 1][(kq & 1)*16 + 32];
        unsigned long long acc[4][2];
#pragma unroll
        for (int g = 0; g < 4; g++){ acc[g][0] = 0ull; acc[g][1] = 0ull; }
#pragma unroll
        for (int q = 0; q < 4; q++){
            ulonglong2 hb0 = h0[q];
            ulonglong2 hb1 = h1[q];
#pragma unroll
            for (int g = 0; g < 4; g++){
                fma2(acc[g][0], wreg[g][2*q  ], hb0.x);
                fma2(acc[g][0], wreg[g][2*q+1], hb0.y);
                fma2(acc[g][1], wreg[g][2*q  ], hb1.x);
                fma2(acc[g][1], wreg[g][2*q+1], hb1.y);
            }
        }

        // --- collapse to f32; 4-level butterfly over 16 kq lanes ---
        float s[4][2];
#pragma unroll
        for (int g = 0; g < 4; g++){
            float2 f0 = up2(acc[g][0]); s[g][0] = f0.x + f0.y;
            float2 f1 = up2(acc[g][1]); s[g][1] = f1.x + f1.y;
        }
        // L1 (xor 4): batch
        float a0 = s[0][b_c] + __shfl_xor_sync(0xffffffffu, s[0][b_c^1], 4);
        float a1 = s[1][b_c] + __shfl_xor_sync(0xffffffffu, s[1][b_c^1], 4);
        float a2 = s[2][b_c] + __shfl_xor_sync(0xffffffffu, s[2][b_c^1], 4);
        float a3 = s[3][b_c] + __shfl_xor_sync(0xffffffffu, s[3][b_c^1], 4);
        // L2 (xor 2): gate-high
        int gh = (kq >> 1) & 1;
        float k0 = gh ? a2 : a0, k1 = gh ? a3 : a1;
        float x0 = gh ? a0 : a2, x1 = gh ? a1 : a3;
        float m0 = k0 + __shfl_xor_sync(0xffffffffu, x0, 2);
        float m1 = k1 + __shfl_xor_sync(0xffffffffu, x1, 2);
        // L3 (xor 1): gate-low
        int gl = kq & 1;
        float keep = gl ? m1 : m0;
        float send = gl ? m0 : m1;
        float fin = keep + __shfl_xor_sync(0xffffffffu, send, 1);
        // L4 (xor 8): combine the two K-halves (dup lanes)
        float s_val = fin + __shfl_xor_sync(0xffffffffu, fin, 8) + pre;

        // --- gather 4 gates for (u_lo, b_c) ---
        int base = (lane & 16) | (b_c << 2);
        float gi = __shfl_sync(0xffffffffu, s_val, base + 0);
        float gj = __shfl_sync(0xffffffffu, s_val, base + 1);
        float gf = __shfl_sync(0xffffffffu, s_val, base + 2);
        float go = __shfl_sync(0xffffffffu, s_val, base + 3);

        // --- activation (meaningful on writer lanes) ---
        float sf = sigf(gf + 1.0f);
        float si = sigf(gi);
        float tj = tanh_fast(gj);
        float so = sigf(go);
        float nc = c_r * sf + si * tj;
        float nh = tanh_fast(nc) * so;
        bool mask = (t < slen);
        if (mask){ c_r = nc; h_r = nh; }
        float oval = mask ? nh : 0.f;

        // --- sends FIRST (critical path) ---
        float v_lo = __shfl_sync(0xffffffffu, h_r, src_lo);
        float v_hi = __shfl_sync(0xffffffffu, h_r, src_hi);
        if (is_snd && t + 1 < T_)
            st_async64(dst_base + (unsigned)(p^1)*PHASE_B, pk2(v_lo, v_hi),
                       dst_bar + (unsigned)(p^1)*8);

        // --- output store (off critical path) ---
        float o_hi = __shfl_sync(0xffffffffu, oval, lane | 16);
        if (is_wr2)
            *(float2*)&out[LAST_OFF + ((size_t)bg_c*T_ + t)*H_ + u] =
                make_float2(oval, o_hi);

        pre = pre_n;
    }

    if (is_wr){
        out[C_OFF  + (size_t)bg_c*H_ + u] = c_r;
        out[HF_OFF + (size_t)bg_c*H_ + u] = h_r;
    }
    cluster_sync_();   // no CTA exits while peers may still target its smem
}

// ======================================================================
// Kernel 3: logits = last_layer @ W_out + b_out   [65536,256]@[256,18]
// ======================================================================
#define WO_ST 260

__global__ __launch_bounds__(252) void logits_k(
    const float* __restrict__ Wout, const float* __restrict__ bout,
    float* __restrict__ out)
{
    __shared__ float wo[A_*WO_ST];
    __shared__ float bo[A_];
    int tid = threadIdx.x;
    for (int i = tid; i < H_*A_; i += 252){
        int k = i / A_, a = i % A_;
        wo[a*WO_ST + k] = Wout[(size_t)k*A_ + a];
    }
    if (tid < A_) bo[tid] = bout[tid];
    __syncthreads();

    int r = blockIdx.x*14 + tid/A_;
    int a = tid % A_;
    if (r >= M_) return;
    const float* hrow = out + LAST_OFF + (size_t)r*H_;
    const float* wa = wo + a*WO_ST;
    unsigned long long acc = 0ull;
#pragma unroll
    for (int k4 = 0; k4 < H_/4; k4++){
        float4 hv = *(const float4*)&hrow[k4*4];
        float4 wv = *(const float4*)&wa[k4*4];
        fma2(acc, pk2(hv.x,hv.y), pk2(wv.x,wv.y));
        fma2(acc, pk2(hv.z,hv.w), pk2(wv.z,wv.w));
    }
    float2 s = up2(acc);
    out[(size_t)r*A_ + a] = s.x + s.y + bo[a];
}

// ======================================================================
extern "C" void kernel_launch(void* const* d_in, const int* in_sizes, int n_in,
                              void* d_out, int out_size)
{
    const float* x     = (const float*)d_in[0];
    const int*   seq   = (const int*)  d_in[1];
    const float* c_in  = (const float*)d_in[2];
    const float* h_in  = (const float*)d_in[3];
    const float* W     = (const float*)d_in[4];
    const float* b     = (const float*)d_in[5];
    const float* Wout  = (const float*)d_in[6];
    const float* bout  = (const float*)d_in[7];
    float* out = (float*)d_out;

    pregemm_k<<<dim3(G4/PG_BN, M_/PG_BM), 256>>>(x, W, b);
    lstm_rec_k<<<128, 512>>>(W, seq, c_in, h_in, out);
    logits_k<<<(M_ + 13)/14, 252>>>(Wout, bout, out);
}